// round 16
// baseline (speedup 1.0000x reference)
#include <cuda_runtime.h>
#include <cuda_fp16.h>

#define N_  4
#define C_  128
#define HW_ 4096
#define W_  64

union Half4 {
    uint2   u;
    __half2 h[2];
};

// ---------------------------------------------------------------------------
// Single fused kernel, cluster-shared validity (R14) + early cluster-arrive.
// 32 clusters x 4 CTAs (rank = n), 1024 threads/CTA; CTA = (n, channel-quad).
// Each CTA reads ONLY its own grid row; .all(0) validity across the 4 grids
// is assembled by exchanging bitmasks over DSMEM and ANDing.
// barrier.cluster.arrive is issued immediately after the last smem store so
// peer CTAs' waits release as early as possible; tap math overlaps the wait.
// Smem tile: s[j] = half4(x[ch0..ch0+3][j]) -> one LDS.64 per corner serves
// 4 channels. Thread t: positions 4t..4t+3; all gmem ops 128-bit. fp32 math.
// out = w0*x[c] + w1*x[c+1] + w2*x[c+64] + w3*x[c+65],
// w = outer([1-fx, fx], [fx, fy]) * valid
// ---------------------------------------------------------------------------
__global__ __launch_bounds__(1024, 1) __cluster_dims__(4, 1, 1)
void fused_kernel(const float* __restrict__ x,
                  const float* __restrict__ grid,
                  float* __restrict__ out) {
    __shared__ uint2    s[HW_];      // 32 KB: half4 per position
    __shared__ unsigned vm[4][128];  // 2 KB: per-rank validity bitmasks

    const int tid = threadIdx.x;        // 0..1023
    const int bid = blockIdx.x;         // 0..127
    const int n   = bid & 3;            // cluster rank == grid index
    const int ch0 = (bid >> 2) * 4;     // channel-quad base

    const float4* r0 = (const float4*)(x + (size_t)(n * C_ + ch0 + 0) * HW_);
    const float4* r1 = (const float4*)(x + (size_t)(n * C_ + ch0 + 1) * HW_);
    const float4* r2 = (const float4*)(x + (size_t)(n * C_ + ch0 + 2) * HW_);
    const float4* r3 = (const float4*)(x + (size_t)(n * C_ + ch0 + 3) * HW_);

    // ---- x staging loads (4x LDG.128, issue first)
    float4 v0 = __ldg(r0 + tid);
    float4 v1 = __ldg(r1 + tid);
    float4 v2 = __ldg(r2 + tid);
    float4 v3 = __ldg(r3 + tid);

    // ---- own grid row only (2x LDG.128): positions 4t..4t+3
    const float4* g4 = (const float4*)grid;
    float4 G0 = __ldg(g4 + n * (HW_ / 2) + 2 * tid);       // pos 4t, 4t+1
    float4 G1 = __ldg(g4 + n * (HW_ / 2) + 2 * tid + 1);   // pos 4t+2, 4t+3

    // ---- own-row in-range nibble (bit b = position 4t+b in range)
    unsigned nib =
        ((G0.x >= -0.001f && G0.x <= 63.001f && G0.y >= -0.001f && G0.y <= 63.001f) ? 1u : 0u) |
        ((G0.z >= -0.001f && G0.z <= 63.001f && G0.w >= -0.001f && G0.w <= 63.001f) ? 2u : 0u) |
        ((G1.x >= -0.001f && G1.x <= 63.001f && G1.y >= -0.001f && G1.y <= 63.001f) ? 4u : 0u) |
        ((G1.z >= -0.001f && G1.z <= 63.001f && G1.w >= -0.001f && G1.w <= 63.001f) ? 8u : 0u);

    // ---- assemble 32-position words within 8-lane groups (no atomics)
    unsigned wv = nib << (4 * (tid & 7));
    wv |= __shfl_xor_sync(0xFFFFFFFFu, wv, 4);
    wv |= __shfl_xor_sync(0xFFFFFFFFu, wv, 2);
    wv |= __shfl_xor_sync(0xFFFFFFFFu, wv, 1);
    if ((tid & 7) == 0) {
        int w = tid >> 3;                 // word index 0..127
        vm[n][w] = wv;                    // local copy
        unsigned la = (unsigned)__cvta_generic_to_shared(&vm[n][w]);
#pragma unroll
        for (int r = 0; r < 4; ++r) {
            if (r != n) {
                unsigned ra;
                asm volatile("mapa.shared::cluster.u32 %0, %1, %2;"
                             : "=r"(ra) : "r"(la), "r"(r));
                asm volatile("st.shared::cluster.u32 [%0], %1;"
                             :: "r"(ra), "r"(wv) : "memory");
            }
        }
    }

    // ---- stage x as half4 quads (2x STS.128, conflict-free)
    {
        Half4 q0, q1, q2, q3;
        q0.h[0] = __floats2half2_rn(v0.x, v1.x);  q0.h[1] = __floats2half2_rn(v2.x, v3.x);
        q1.h[0] = __floats2half2_rn(v0.y, v1.y);  q1.h[1] = __floats2half2_rn(v2.y, v3.y);
        q2.h[0] = __floats2half2_rn(v0.z, v1.z);  q2.h[1] = __floats2half2_rn(v2.z, v3.z);
        q3.h[0] = __floats2half2_rn(v0.w, v1.w);  q3.h[1] = __floats2half2_rn(v2.w, v3.w);
        uint4* sd = (uint4*)&s[4 * tid];
        sd[0] = make_uint4(q0.u.x, q0.u.y, q1.u.x, q1.u.y);
        sd[1] = make_uint4(q2.u.x, q2.u.y, q3.u.x, q3.u.y);
    }

    // ---- ARRIVE as early as possible (all smem stores done); peers' waits
    //      release without waiting for our tap math.
    asm volatile("barrier.cluster.arrive.aligned;" ::: "memory");

    // ---- tap math from own row (overlaps cluster wait)
    int   c0[4];
    float fx[4], fy[4];
#pragma unroll
    for (int p = 0; p < 4; ++p) {
        float2 go = (p == 0) ? make_float2(G0.x, G0.y)
                  : (p == 1) ? make_float2(G0.z, G0.w)
                  : (p == 2) ? make_float2(G1.x, G1.y)
                  :            make_float2(G1.z, G1.w);
        float xx = fminf(fmaxf(go.x, 0.001f), 62.999f);
        float yy = fminf(fmaxf(go.y, 0.001f), 62.999f);
        float flx = floorf(xx);
        float fly = floorf(yy);
        c0[p] = (int)flx * W_ + (int)fly;
        fx[p] = xx - flx;
        fy[p] = yy - fly;
    }

    asm volatile("barrier.cluster.wait.aligned;" ::: "memory");

    // ---- fold validity (AND of all 4 ranks) into fx,fy
    {
        int w  = tid >> 3;
        int sh = 4 * (tid & 7);
        unsigned va = vm[0][w] & vm[1][w] & vm[2][w] & vm[3][w];
        unsigned nb = (va >> sh) & 0xFu;
#pragma unroll
        for (int p = 0; p < 4; ++p) {
            float vf = (float)((nb >> p) & 1u);
            fx[p] *= vf;
            fy[p] *= vf;
        }
    }

    // ---- gather + fp32 math: per position 4 corners (LDS.64)
    float4 oc0, oc1, oc2, oc3;
    float* po0 = (float*)&oc0;
    float* po1 = (float*)&oc1;
    float* po2 = (float*)&oc2;
    float* po3 = (float*)&oc3;
#pragma unroll
    for (int p = 0; p < 4; ++p) {
        int c = c0[p];
        Half4 t0, t1, t2, t3;
        t0.u = s[c];
        t1.u = s[c + 1];
        t2.u = s[c + 64];
        t3.u = s[c + 65];

        float w0 = (1.f - fx[p]) * fx[p];
        float w1 = (1.f - fx[p]) * fy[p];
        float w2 = fx[p] * fx[p];
        float w3 = fx[p] * fy[p];

        float2 a01 = __half22float2(t0.h[0]), a23 = __half22float2(t0.h[1]);
        float2 b01 = __half22float2(t1.h[0]), b23 = __half22float2(t1.h[1]);
        float2 c01 = __half22float2(t2.h[0]), c23 = __half22float2(t2.h[1]);
        float2 d01 = __half22float2(t3.h[0]), d23 = __half22float2(t3.h[1]);

        po0[p] = w0 * a01.x + w1 * b01.x + w2 * c01.x + w3 * d01.x;
        po1[p] = w0 * a01.y + w1 * b01.y + w2 * c01.y + w3 * d01.y;
        po2[p] = w0 * a23.x + w1 * b23.x + w2 * c23.x + w3 * d23.x;
        po3[p] = w0 * a23.y + w1 * b23.y + w2 * c23.y + w3 * d23.y;
    }

    float4* ob = (float4*)(out + (size_t)(n * C_ + ch0) * HW_);
    const int q = HW_ / 4;
    ob[0 * q + tid] = oc0;
    ob[1 * q + tid] = oc1;
    ob[2 * q + tid] = oc2;
    ob[3 * q + tid] = oc3;
}

extern "C" void kernel_launch(void* const* d_in, const int* in_sizes, int n_in,
                              void* d_out, int out_size) {
    const float* x    = (const float*)d_in[0];   // (4, 128, 4096) f32
    const float* grid = (const float*)d_in[1];   // (4, 64, 64, 2) f32
    float* out = (float*)d_out;                  // (4, 128, 4096) f32

    fused_kernel<<<N_ * (C_ / 4), 1024>>>(x, grid, out);
}

// round 17
// speedup vs baseline: 1.1402x; 1.1402x over previous
#include <cuda_runtime.h>
#include <cuda_fp16.h>

#define N_  4
#define C_  128
#define HW_ 4096
#define W_  64

union Half4 {
    uint2   u;
    __half2 h[2];
};

// ---------------------------------------------------------------------------
// Single fused kernel, cluster-shared validity (R14) + batched gather LDS.
// 32 clusters x 4 CTAs (rank = n), 1024 threads/CTA; CTA = (n, channel-quad).
// Each CTA reads ONLY its own grid row; .all(0) validity across the 4 grids
// is assembled by exchanging bitmasks over DSMEM and ANDing.
// Smem tile: s[j] = half4(x[ch0..ch0+3][j]) -> one LDS.64 per corner serves
// 4 channels. ALL 16 gather LDS issued back-to-back (t[16]) before any math
// so their latency overlaps. fp32 math. All gmem ops 128-bit.
// out = w0*x[c] + w1*x[c+1] + w2*x[c+64] + w3*x[c+65],
// w = outer([1-fx, fx], [fx, fy]) * valid
// ---------------------------------------------------------------------------
__global__ __launch_bounds__(1024, 1) __cluster_dims__(4, 1, 1)
void fused_kernel(const float* __restrict__ x,
                  const float* __restrict__ grid,
                  float* __restrict__ out) {
    __shared__ uint2    s[HW_];      // 32 KB: half4 per position
    __shared__ unsigned vm[4][128];  // 2 KB: per-rank validity bitmasks

    const int tid = threadIdx.x;        // 0..1023
    const int bid = blockIdx.x;         // 0..127
    const int n   = bid & 3;            // cluster rank == grid index
    const int ch0 = (bid >> 2) * 4;     // channel-quad base

    const float4* r0 = (const float4*)(x + (size_t)(n * C_ + ch0 + 0) * HW_);
    const float4* r1 = (const float4*)(x + (size_t)(n * C_ + ch0 + 1) * HW_);
    const float4* r2 = (const float4*)(x + (size_t)(n * C_ + ch0 + 2) * HW_);
    const float4* r3 = (const float4*)(x + (size_t)(n * C_ + ch0 + 3) * HW_);

    // ---- x staging loads (4x LDG.128, issue first)
    float4 v0 = __ldg(r0 + tid);
    float4 v1 = __ldg(r1 + tid);
    float4 v2 = __ldg(r2 + tid);
    float4 v3 = __ldg(r3 + tid);

    // ---- own grid row only (2x LDG.128): positions 4t..4t+3
    const float4* g4 = (const float4*)grid;
    float4 G0 = __ldg(g4 + n * (HW_ / 2) + 2 * tid);       // pos 4t, 4t+1
    float4 G1 = __ldg(g4 + n * (HW_ / 2) + 2 * tid + 1);   // pos 4t+2, 4t+3

    // ---- own-row in-range nibble (bit b = position 4t+b in range)
    unsigned nib =
        ((G0.x >= -0.001f && G0.x <= 63.001f && G0.y >= -0.001f && G0.y <= 63.001f) ? 1u : 0u) |
        ((G0.z >= -0.001f && G0.z <= 63.001f && G0.w >= -0.001f && G0.w <= 63.001f) ? 2u : 0u) |
        ((G1.x >= -0.001f && G1.x <= 63.001f && G1.y >= -0.001f && G1.y <= 63.001f) ? 4u : 0u) |
        ((G1.z >= -0.001f && G1.z <= 63.001f && G1.w >= -0.001f && G1.w <= 63.001f) ? 8u : 0u);

    // ---- assemble 32-position words within 8-lane groups (no atomics)
    unsigned wv = nib << (4 * (tid & 7));
    wv |= __shfl_xor_sync(0xFFFFFFFFu, wv, 4);
    wv |= __shfl_xor_sync(0xFFFFFFFFu, wv, 2);
    wv |= __shfl_xor_sync(0xFFFFFFFFu, wv, 1);
    if ((tid & 7) == 0) {
        int w = tid >> 3;                 // word index 0..127
        vm[n][w] = wv;                    // local copy
        unsigned la = (unsigned)__cvta_generic_to_shared(&vm[n][w]);
#pragma unroll
        for (int r = 0; r < 4; ++r) {
            if (r != n) {
                unsigned ra;
                asm volatile("mapa.shared::cluster.u32 %0, %1, %2;"
                             : "=r"(ra) : "r"(la), "r"(r));
                asm volatile("st.shared::cluster.u32 [%0], %1;"
                             :: "r"(ra), "r"(wv) : "memory");
            }
        }
    }

    // ---- stage x as half4 quads (2x STS.128, conflict-free)
    {
        Half4 q0, q1, q2, q3;
        q0.h[0] = __floats2half2_rn(v0.x, v1.x);  q0.h[1] = __floats2half2_rn(v2.x, v3.x);
        q1.h[0] = __floats2half2_rn(v0.y, v1.y);  q1.h[1] = __floats2half2_rn(v2.y, v3.y);
        q2.h[0] = __floats2half2_rn(v0.z, v1.z);  q2.h[1] = __floats2half2_rn(v2.z, v3.z);
        q3.h[0] = __floats2half2_rn(v0.w, v1.w);  q3.h[1] = __floats2half2_rn(v2.w, v3.w);
        uint4* sd = (uint4*)&s[4 * tid];
        sd[0] = make_uint4(q0.u.x, q0.u.y, q1.u.x, q1.u.y);
        sd[1] = make_uint4(q2.u.x, q2.u.y, q3.u.x, q3.u.y);
    }

    // ---- tap math from own row (validity applied after cluster sync)
    int   c0[4];
    float fx[4], fy[4];
#pragma unroll
    for (int p = 0; p < 4; ++p) {
        float2 go = (p == 0) ? make_float2(G0.x, G0.y)
                  : (p == 1) ? make_float2(G0.z, G0.w)
                  : (p == 2) ? make_float2(G1.x, G1.y)
                  :            make_float2(G1.z, G1.w);
        float xx = fminf(fmaxf(go.x, 0.001f), 62.999f);
        float yy = fminf(fmaxf(go.y, 0.001f), 62.999f);
        float flx = floorf(xx);
        float fly = floorf(yy);
        c0[p] = (int)flx * W_ + (int)fly;
        fx[p] = xx - flx;
        fy[p] = yy - fly;
    }

    // ---- cluster barrier: release our (mask + tile) stores, acquire peers'
    asm volatile("barrier.cluster.arrive.aligned;" ::: "memory");
    asm volatile("barrier.cluster.wait.aligned;"   ::: "memory");

    // ---- fold validity (AND of all 4 ranks) into fx,fy
    {
        int w  = tid >> 3;
        int sh = 4 * (tid & 7);
        unsigned va = vm[0][w] & vm[1][w] & vm[2][w] & vm[3][w];
        unsigned nb = (va >> sh) & 0xFu;
#pragma unroll
        for (int p = 0; p < 4; ++p) {
            float vf = (float)((nb >> p) & 1u);
            fx[p] *= vf;
            fy[p] *= vf;
        }
    }

    // ---- gather: issue ALL 16 LDS.64 back-to-back (full MLP)
    Half4 t[16];
#pragma unroll
    for (int p = 0; p < 4; ++p) {
        int c = c0[p];
        t[4 * p + 0].u = s[c];
        t[4 * p + 1].u = s[c + 1];
        t[4 * p + 2].u = s[c + 64];
        t[4 * p + 3].u = s[c + 65];
    }

    // ---- math (dependency-free of further LDS)
    float4 oc0, oc1, oc2, oc3;
    float* po0 = (float*)&oc0;
    float* po1 = (float*)&oc1;
    float* po2 = (float*)&oc2;
    float* po3 = (float*)&oc3;
#pragma unroll
    for (int p = 0; p < 4; ++p) {
        float w0 = (1.f - fx[p]) * fx[p];
        float w1 = (1.f - fx[p]) * fy[p];
        float w2 = fx[p] * fx[p];
        float w3 = fx[p] * fy[p];

        float2 a01 = __half22float2(t[4 * p + 0].h[0]), a23 = __half22float2(t[4 * p + 0].h[1]);
        float2 b01 = __half22float2(t[4 * p + 1].h[0]), b23 = __half22float2(t[4 * p + 1].h[1]);
        float2 c01 = __half22float2(t[4 * p + 2].h[0]), c23 = __half22float2(t[4 * p + 2].h[1]);
        float2 d01 = __half22float2(t[4 * p + 3].h[0]), d23 = __half22float2(t[4 * p + 3].h[1]);

        po0[p] = w0 * a01.x + w1 * b01.x + w2 * c01.x + w3 * d01.x;
        po1[p] = w0 * a01.y + w1 * b01.y + w2 * c01.y + w3 * d01.y;
        po2[p] = w0 * a23.x + w1 * b23.x + w2 * c23.x + w3 * d23.x;
        po3[p] = w0 * a23.y + w1 * b23.y + w2 * c23.y + w3 * d23.y;
    }

    float4* ob = (float4*)(out + (size_t)(n * C_ + ch0) * HW_);
    const int q = HW_ / 4;
    ob[0 * q + tid] = oc0;
    ob[1 * q + tid] = oc1;
    ob[2 * q + tid] = oc2;
    ob[3 * q + tid] = oc3;
}

extern "C" void kernel_launch(void* const* d_in, const int* in_sizes, int n_in,
                              void* d_out, int out_size) {
    const float* x    = (const float*)d_in[0];   // (4, 128, 4096) f32
    const float* grid = (const float*)d_in[1];   // (4, 64, 64, 2) f32
    float* out = (float*)d_out;                  // (4, 128, 4096) f32

    fused_kernel<<<N_ * (C_ / 4), 1024>>>(x, grid, out);
}